// round 1
// baseline (speedup 1.0000x reference)
#include <cuda_runtime.h>

// Problem constants (fixed shapes)
#define BB 4
#define NN 4096
#define MM 4096
#define CC 256
#define CAP 512   // max valid keys per row we track (statistical max ~40)

// ---------------- scratch (static device globals; no allocations) ----------------
__device__ float g_G[CC * CC];      // (Wq^T Wk) / 16
__device__ float g_Wvm[CC * CC];    // Wm @ Wv
__device__ float g_kq[CC];          // (Wk^T bq) / 16
__device__ float g_bout[CC];        // Wm @ bv + bm
__device__ float g_T[BB * NN * CC]; // nodes_L @ G + kq
__device__ float g_S[BB * NN * CC]; // softmax-weighted sum of nodes_R rows
__device__ float g_meanR[BB * CC];
__device__ float g_muR[BB];
__device__ float g_part[BB * 64 * CC];
__device__ float g_partu[BB * 64];

// ---------------- small weight prep: G, Wvm, kq, bout ----------------
__global__ void prep_kernel(const float* __restrict__ Wq, const float* __restrict__ Wk,
                            const float* __restrict__ Wv, const float* __restrict__ Wm,
                            const float* __restrict__ bq, const float* __restrict__ bv,
                            const float* __restrict__ bm) {
    int bx = blockIdx.x, j = threadIdx.x;
    if (bx < 256) {
        // G[i][j] = sum_k Wq[k][i] * Wk[k][j]  (i = bx)
        float s = 0.f;
        #pragma unroll 8
        for (int k = 0; k < 256; k++) s += Wq[k * 256 + bx] * Wk[k * 256 + j];
        g_G[bx * 256 + j] = s * 0.0625f;
    } else if (bx < 512) {
        int i = bx - 256;
        // Wvm[i][j] = sum_k Wm[i][k] * Wv[k][j]
        float s = 0.f;
        #pragma unroll 8
        for (int k = 0; k < 256; k++) s += Wm[i * 256 + k] * Wv[k * 256 + j];
        g_Wvm[i * 256 + j] = s;
    } else {
        float s = 0.f, t = 0.f;
        for (int k = 0; k < 256; k++) {
            s += Wk[k * 256 + j] * bq[k];
            t += Wm[j * 256 + k] * bv[k];
        }
        g_kq[j] = s * 0.0625f;
        g_bout[j] = t + bm[j];
    }
}

// ---------------- batch means of nodes_R and u_R (deterministic 2-pass) ----------------
__global__ void mean_part_kernel(const float* __restrict__ nodesR, const float* __restrict__ kptsR) {
    int b = blockIdx.y, p = blockIdx.x, c = threadIdx.x;
    const float* base = nodesR + ((size_t)b * MM + (size_t)p * 64) * CC;
    float s = 0.f;
    #pragma unroll 4
    for (int r = 0; r < 64; r++) s += base[r * CC + c];
    g_part[(b * 64 + p) * CC + c] = s;
    if (c == 0) {
        const float* kb = kptsR + ((size_t)b * MM + (size_t)p * 64) * 2;
        float su = 0.f;
        for (int r = 0; r < 64; r++) su += kb[r * 2];
        g_partu[b * 64 + p] = su;
    }
}

__global__ void mean_red_kernel() {
    int b = blockIdx.x, c = threadIdx.x;
    float s = 0.f;
    for (int p = 0; p < 64; p++) s += g_part[(b * 64 + p) * CC + c];
    g_meanR[b * CC + c] = s * (1.0f / MM);
    if (c == 0) {
        float su = 0.f;
        for (int p = 0; p < 64; p++) su += g_partu[b * 64 + p];
        g_muR[b] = su * (1.0f / MM);
    }
}

// ---------------- fp32 SGEMM: [16384 x 256] @ [256 x 256] ----------------
// TRANSB=false: C = A @ g_G + g_kq, writes g_T            (A = nodes_L)
// TRANSB=true : C = g_S @ g_Wvm^T + g_bout, writes Cparam (Cparam = d_out)
template <bool TRANSB>
__global__ __launch_bounds__(256) void sgemm_kernel(const float* __restrict__ Aparam,
                                                    float* __restrict__ Cparam) {
    __shared__ float As[16][128];
    __shared__ float Bs[16][64];

    const float* A    = TRANSB ? g_S   : Aparam;
    const float* Bm   = TRANSB ? g_Wvm : g_G;
    const float* bias = TRANSB ? g_bout : g_kq;
    float*       C    = TRANSB ? Cparam : g_T;

    int tid = threadIdx.x;
    int tx = tid & 15, ty = tid >> 4;
    int rowBase = blockIdx.y * 128, colBase = blockIdx.x * 64;

    int aRow = tid >> 2, aK = (tid & 3) << 2;
    const float* Aptr = A + (size_t)(rowBase + aRow) * 256 + aK;

    float acc[8][4];
    #pragma unroll
    for (int i = 0; i < 8; i++)
        #pragma unroll
        for (int j = 0; j < 4; j++) acc[i][j] = 0.f;

    float4 ra0, ra1, rb;
    int bn = TRANSB ? (tid >> 2) : 0;
    int bkk = TRANSB ? ((tid & 3) << 2) : 0;
    int bK = TRANSB ? 0 : (tid >> 4);
    int bN4 = TRANSB ? 0 : ((tid & 15) << 2);

    // prefetch tile 0
    {
        ra0 = *(const float4*)(Aptr);
        ra1 = *(const float4*)(Aptr + 64 * 256);
        if (!TRANSB) rb = *(const float4*)&Bm[(size_t)bK * 256 + colBase + bN4];
        else         rb = *(const float4*)&Bm[(size_t)(colBase + bn) * 256 + bkk];
    }

    #pragma unroll 1
    for (int kt = 0; kt < 16; kt++) {
        // store staged tile
        As[aK + 0][aRow] = ra0.x; As[aK + 1][aRow] = ra0.y;
        As[aK + 2][aRow] = ra0.z; As[aK + 3][aRow] = ra0.w;
        As[aK + 0][aRow + 64] = ra1.x; As[aK + 1][aRow + 64] = ra1.y;
        As[aK + 2][aRow + 64] = ra1.z; As[aK + 3][aRow + 64] = ra1.w;
        if (!TRANSB) {
            *(float4*)&Bs[bK][bN4] = rb;
        } else {
            Bs[bkk + 0][bn] = rb.x; Bs[bkk + 1][bn] = rb.y;
            Bs[bkk + 2][bn] = rb.z; Bs[bkk + 3][bn] = rb.w;
        }
        __syncthreads();

        if (kt < 15) {
            int k0 = (kt + 1) * 16;
            ra0 = *(const float4*)(Aptr + k0);
            ra1 = *(const float4*)(Aptr + 64 * 256 + k0);
            if (!TRANSB) rb = *(const float4*)&Bm[(size_t)(k0 + bK) * 256 + colBase + bN4];
            else         rb = *(const float4*)&Bm[(size_t)(colBase + bn) * 256 + k0 + bkk];
        }

        #pragma unroll
        for (int k = 0; k < 16; k++) {
            float4 a0 = *(const float4*)&As[k][ty * 8];
            float4 a1 = *(const float4*)&As[k][ty * 8 + 4];
            float4 b4 = *(const float4*)&Bs[k][tx * 4];
            float av[8] = {a0.x, a0.y, a0.z, a0.w, a1.x, a1.y, a1.z, a1.w};
            float bv4[4] = {b4.x, b4.y, b4.z, b4.w};
            #pragma unroll
            for (int i = 0; i < 8; i++)
                #pragma unroll
                for (int j = 0; j < 4; j++) acc[i][j] += av[i] * bv4[j];
        }
        __syncthreads();
    }

    float4 bb = *(const float4*)&bias[colBase + tx * 4];
    #pragma unroll
    for (int i = 0; i < 8; i++) {
        float4 o;
        o.x = acc[i][0] + bb.x; o.y = acc[i][1] + bb.y;
        o.z = acc[i][2] + bb.z; o.w = acc[i][3] + bb.w;
        *(float4*)&C[(size_t)(rowBase + ty * 8 + i) * 256 + colBase + tx * 4] = o;
    }
}

// ---------------- sparse masked attention ----------------
// One block handles 8 query rows of one batch. kpts_R[b] cached in SMEM.
__global__ __launch_bounds__(256) void attn_kernel(const float* __restrict__ nodesR,
                                                   const float* __restrict__ kptsL,
                                                   const float* __restrict__ kptsR,
                                                   float* __restrict__ out,
                                                   size_t disp_off, size_t conf_off) {
    __shared__ float s_ku[MM];
    __shared__ float s_kv[MM];
    __shared__ float s_tq[CC];
    __shared__ int   s_idx[CAP];
    __shared__ float s_w[CAP];
    __shared__ int   s_wsum[8];
    __shared__ int   s_total;
    __shared__ float s_red[2];

    int tid = threadIdx.x, lane = tid & 31, w = tid >> 5;
    int bx = blockIdx.x;
    int b = bx >> 9;              // 512 tiles per batch
    int n0 = (bx & 511) << 3;     // 8 rows per tile

    const float* kR = kptsR + (size_t)b * MM * 2;
    for (int m = tid; m < MM; m += 256) {
        float2 p = *(const float2*)(kR + m * 2);
        s_ku[m] = p.x; s_kv[m] = p.y;
    }
    const float* nR = nodesR + (size_t)b * MM * CC;

    for (int r = 0; r < 8; r++) {
        int rowg = b * NN + n0 + r;
        float2 kl = *(const float2*)(kptsL + (size_t)rowg * 2);
        float uL = kl.x, vL = kl.y;
        __syncthreads();   // protects SMEM reuse across r (and kpts load for r=0)

        s_tq[tid] = g_T[(size_t)rowg * CC + tid];

        // count valid keys (strided: thread t covers m = i*256 + t -> conflict-free SMEM)
        int cnt = 0;
        #pragma unroll
        for (int i = 0; i < 16; i++) {
            int m = i * 256 + tid;
            float du = uL - s_ku[m];
            cnt += (int)((fabsf(vL - s_kv[m]) < 3.0f) & (du > 0.0f) & (du < 192.0f));
        }
        // block exclusive scan
        int x = cnt;
        #pragma unroll
        for (int off = 1; off < 32; off <<= 1) {
            int y = __shfl_up_sync(0xffffffffu, x, off);
            if (lane >= off) x += y;
        }
        if (lane == 31) s_wsum[w] = x;
        __syncthreads();
        if (w == 0 && lane < 8) {
            int ws = s_wsum[lane], xs = ws;
            #pragma unroll
            for (int off = 1; off < 8; off <<= 1) {
                int y = __shfl_up_sync(0xffu, xs, off);
                if (lane >= off) xs += y;
            }
            s_wsum[lane] = xs - ws;
            if (lane == 7) s_total = xs;
        }
        __syncthreads();
        int pos = s_wsum[w] + x - cnt;
        #pragma unroll
        for (int i = 0; i < 16; i++) {
            int m = i * 256 + tid;
            float du = uL - s_ku[m];
            bool val = (fabsf(vL - s_kv[m]) < 3.0f) && (du > 0.0f) && (du < 192.0f);
            if (val) { if (pos < CAP) s_idx[pos] = m; pos++; }
        }
        __syncthreads();
        int nv = min(s_total, CAP);

        if (nv > 0) {
            // logits: one warp per valid key, fp32-exact dot over 256
            for (int e = w; e < nv; e += 8) {
                const float4* p = (const float4*)(nR + (size_t)s_idx[e] * CC);
                float4 x0 = p[lane * 2], x1 = p[lane * 2 + 1];
                const float4* tq4 = (const float4*)s_tq;
                float4 t0 = tq4[lane * 2], t1 = tq4[lane * 2 + 1];
                float d = x0.x * t0.x + x0.y * t0.y + x0.z * t0.z + x0.w * t0.w
                        + x1.x * t1.x + x1.y * t1.y + x1.z * t1.z + x1.w * t1.w;
                #pragma unroll
                for (int off = 16; off; off >>= 1) d += __shfl_xor_sync(0xffffffffu, d, off);
                if (lane == 0) s_w[e] = d;
            }
            __syncthreads();
            if (tid == 0) {
                float mx = -3.0e38f;
                for (int e = 0; e < nv; e++) mx = fmaxf(mx, s_w[e]);
                s_red[0] = mx;
            }
            __syncthreads();
            for (int e = tid; e < nv; e += 256) s_w[e] = expf(s_w[e] - s_red[0]);
            __syncthreads();
            if (tid == 0) {
                float Wt = 0.f, du = 0.f;
                for (int e = 0; e < nv; e++) {
                    Wt += s_w[e];
                    du += s_w[e] * (uL - s_ku[s_idx[e]]);
                }
                float inv = 1.0f / Wt;
                s_red[1] = inv;
                out[disp_off + rowg] = du * inv;
                out[conf_off + rowg] = 1.0f;
            }
            __syncthreads();
            float acc = 0.f;
            float inv = s_red[1];
            for (int e = 0; e < nv; e++)
                acc += s_w[e] * nR[(size_t)s_idx[e] * CC + tid];
            g_S[(size_t)rowg * CC + tid] = acc * inv;
        } else {
            // all-masked row: softmax over equal logits == uniform 1/M
            g_S[(size_t)rowg * CC + tid] = g_meanR[b * CC + tid];
            if (tid == 0) {
                out[disp_off + rowg] = uL - g_muR[b];
                out[conf_off + rowg] = 0.0f;
            }
        }
    }
}

// ---------------- launch ----------------
extern "C" void kernel_launch(void* const* d_in, const int* in_sizes, int n_in,
                              void* d_out, int out_size) {
    (void)in_sizes; (void)n_in;
    const float* nodes_L = (const float*)d_in[0];
    const float* nodes_R = (const float*)d_in[1];
    const float* kpts_L  = (const float*)d_in[2];
    const float* kpts_R  = (const float*)d_in[3];
    const float* Wq = (const float*)d_in[4];
    const float* bq = (const float*)d_in[5];
    const float* Wk = (const float*)d_in[6];
    // bk (d_in[7]) contributes only a per-query-row constant to the logits:
    // softmax-invariant, so it is intentionally unused.
    const float* Wv = (const float*)d_in[8];
    const float* bv = (const float*)d_in[9];
    const float* Wm = (const float*)d_in[10];
    const float* bm = (const float*)d_in[11];
    float* out = (float*)d_out;

    size_t rows = (size_t)BB * NN;
    size_t disp_off = (size_t)out_size - 2 * rows;  // matched [B*N*C] | disp [B*N] | conf [B*N]
    size_t conf_off = disp_off + rows;

    prep_kernel<<<513, 256>>>(Wq, Wk, Wv, Wm, bq, bv, bm);
    mean_part_kernel<<<dim3(64, BB), 256>>>(nodes_R, kpts_R);
    mean_red_kernel<<<BB, 256>>>();
    sgemm_kernel<false><<<dim3(4, 128), 256>>>(nodes_L, nullptr);   // g_T = nodes_L@G + kq
    attn_kernel<<<BB * (NN / 8), 256>>>(nodes_R, kpts_L, kpts_R, out, disp_off, conf_off);
    sgemm_kernel<true><<<dim3(4, 128), 256>>>(nullptr, out);        // out = g_S@Wvm^T + bout
}

// round 9
// speedup vs baseline: 1.4545x; 1.4545x over previous
#include <cuda_runtime.h>
#include <cstdint>

// Problem constants (fixed shapes)
#define BB 4
#define NN 4096
#define MM 4096
#define CC 256
#define CAPW 128   // max valid keys per row tracked (statistical max ~40)

// ---------------- scratch (static device globals; no allocations) ----------------
// NOTE: these are referenced ONLY inside device code. Passing a __device__
// symbol as a kernel argument from host code yields the host shadow address,
// which GB300's ATS silently dereferences to host memory (R8 failure mode).
__device__ float g_Gt[CC * CC];     // Gt[n][k] = G^T, G = (Wq^T Wk)/16
__device__ float g_Wvm[CC * CC];    // Wvm[n][k] = (Wm @ Wv)[n][k]
__device__ float g_kq[CC];          // (Wk^T bq) / 16
__device__ float g_bout[CC];        // Wm @ bv + bm
__device__ uint4 g_GtP[32 * 16 * 32];   // fragment-packed split-bf16 Gt
__device__ uint4 g_WvmP[32 * 16 * 32];  // fragment-packed split-bf16 Wvm
__device__ float g_T[BB * NN * CC]; // nodes_L @ G + kq
__device__ float g_S[BB * NN * CC]; // softmax-weighted sum of nodes_R rows
__device__ float g_meanR[BB * CC];
__device__ float g_muR[BB];
__device__ float g_part[BB * 64 * CC];
__device__ float g_partu[BB * 64];

// ---------------- helpers: fp32 -> (hi, lo) bf16x2 split ----------------
__device__ __forceinline__ void split2(float v0, float v1, uint32_t& h, uint32_t& l) {
    asm("cvt.rn.bf16x2.f32 %0, %1, %2;" : "=r"(h) : "f"(v1), "f"(v0));
    float r0 = v0 - __uint_as_float(h << 16);
    float r1 = v1 - __uint_as_float(h & 0xFFFF0000u);
    asm("cvt.rn.bf16x2.f32 %0, %1, %2;" : "=r"(l) : "f"(r1), "f"(r0));
}

__device__ __forceinline__ void mma16816(float* c, uint32_t a0, uint32_t a1, uint32_t a2,
                                         uint32_t a3, uint32_t b0, uint32_t b1) {
    asm volatile("mma.sync.aligned.m16n8k16.row.col.f32.bf16.bf16.f32 "
                 "{%0,%1,%2,%3}, {%4,%5,%6,%7}, {%8,%9}, {%0,%1,%2,%3};"
                 : "+f"(c[0]), "+f"(c[1]), "+f"(c[2]), "+f"(c[3])
                 : "r"(a0), "r"(a1), "r"(a2), "r"(a3), "r"(b0), "r"(b1));
}

// ---------------- small weight prep: Gt, Wvm, kq, bout ----------------
__global__ void prep_kernel(const float* __restrict__ Wq, const float* __restrict__ Wk,
                            const float* __restrict__ Wv, const float* __restrict__ Wm,
                            const float* __restrict__ bq, const float* __restrict__ bv,
                            const float* __restrict__ bm) {
    int bx = blockIdx.x, j = threadIdx.x;
    if (bx < 256) {
        // Gt[n][k] = (1/16) sum_c Wq[c][k] * Wk[c][n]  (n = bx, k = j)
        float s = 0.f;
        #pragma unroll 8
        for (int c = 0; c < 256; c++) s += Wq[c * 256 + j] * Wk[c * 256 + bx];
        g_Gt[bx * 256 + j] = s * 0.0625f;
    } else if (bx < 512) {
        int i = bx - 256;
        // Wvm[i][j] = sum_k Wm[i][k] * Wv[k][j]
        float s = 0.f;
        #pragma unroll 8
        for (int k = 0; k < 256; k++) s += Wm[i * 256 + k] * Wv[k * 256 + j];
        g_Wvm[i * 256 + j] = s;
    } else {
        float s = 0.f, t = 0.f;
        for (int k = 0; k < 256; k++) {
            s += Wk[k * 256 + j] * bq[k];
            t += Wm[j * 256 + k] * bv[k];
        }
        g_kq[j] = s * 0.0625f;
        g_bout[j] = t + bm[j];
    }
}

// ---------------- pack B matrices into mma fragment layout ----------------
// For n-tile T (8 cols of C), k-step S (k16), lane l:
//   word0/1 = hi bf16x2 of B[T*8 + l/4][S*16 + (l%4)*2 (+8)]
//   word2/3 = lo residual bf16x2 of same elements
__global__ void pack_kernel() {
    int id = blockIdx.x * 512 + threadIdx.x;   // 64 blocks x 512 = 32768
    int lane = id & 31, S = (id >> 5) & 15, T = (id >> 9) & 31, mat = id >> 14;
    const float* src = mat ? g_Wvm : g_Gt;
    int n = T * 8 + (lane >> 2);
    int kb = S * 16 + (lane & 3) * 2;
    const float* p = src + n * 256 + kb;
    uint32_t h0, l0, h1, l1;
    split2(p[0], p[1], h0, l0);
    split2(p[8], p[9], h1, l1);
    (mat ? g_WvmP : g_GtP)[(T * 16 + S) * 32 + lane] = make_uint4(h0, h1, l0, l1);
}

// ---------------- batch means of nodes_R and u_R (deterministic 2-pass) ----------------
__global__ void mean_part_kernel(const float* __restrict__ nodesR, const float* __restrict__ kptsR) {
    int b = blockIdx.y, p = blockIdx.x, c = threadIdx.x;
    const float* base = nodesR + ((size_t)b * MM + (size_t)p * 64) * CC;
    float s = 0.f;
    #pragma unroll 4
    for (int r = 0; r < 64; r++) s += base[r * CC + c];
    g_part[(b * 64 + p) * CC + c] = s;
    if (c == 0) {
        const float* kb = kptsR + ((size_t)b * MM + (size_t)p * 64) * 2;
        float su = 0.f;
        for (int r = 0; r < 64; r++) su += kb[r * 2];
        g_partu[b * 64 + p] = su;
    }
}

__global__ void mean_red_kernel() {
    int b = blockIdx.x, c = threadIdx.x;
    float s = 0.f;
    for (int p = 0; p < 64; p++) s += g_part[(b * 64 + p) * CC + c];
    g_meanR[b * CC + c] = s * (1.0f / MM);
    if (c == 0) {
        float su = 0.f;
        for (int p = 0; p < 64; p++) su += g_partu[b * 64 + p];
        g_muR[b] = su * (1.0f / MM);
    }
}

// ---------------- split-bf16 tensor-core GEMM ----------------
// C[16384 x 256] = A[16384 x 256] @ Bpacked^T + bias
// D = Ah*Bh + Ah*Bl + Al*Bh  (fp32 accurate to ~2^-17)
// CTA = 256 threads = 8 warps; warp tile m16 x n128; CTA tile m64 x n256.
// B fragments come pre-packed (one uint4 LDG per fragment, L2-resident).
// SECOND=false: g_T = Aparam @ Gt^T + kq      (Aparam = nodes_L)
// SECOND=true : Cparam = g_S @ Wvm^T + bout   (Cparam = d_out)
// All device globals are bound HERE, in device code (see note at globals).
template <bool SECOND>
__global__ __launch_bounds__(256) void tgemm_kernel(const float* __restrict__ Aparam,
                                                    float* __restrict__ Cparam) {
    const float* A    = SECOND ? g_S : Aparam;
    const uint4* Bp   = SECOND ? g_WvmP : g_GtP;
    const float* bias = SECOND ? g_bout : g_kq;
    float*       C    = SECOND ? Cparam : g_T;

    int tid = threadIdx.x, lane = tid & 31, wid = tid >> 5;
    int grp = lane >> 2, qp = lane & 3;
    int mBase = blockIdx.x * 64 + (wid & 3) * 16;
    int ntileBase = (wid >> 2) * 16;     // 16 n-tiles of 8 per warp
    int nh = (wid >> 2) * 128;

    const float* Arow0 = A + (size_t)(mBase + grp) * 256 + qp * 2;
    const float* Arow1 = Arow0 + 8 * 256;

    float acc[16][4];
    #pragma unroll
    for (int t = 0; t < 16; t++)
        #pragma unroll
        for (int i = 0; i < 4; i++) acc[t][i] = 0.f;

    #pragma unroll 1
    for (int S = 0; S < 16; S++) {
        int k0 = S * 16;
        float2 v00 = *(const float2*)(Arow0 + k0);
        float2 v10 = *(const float2*)(Arow1 + k0);
        float2 v01 = *(const float2*)(Arow0 + k0 + 8);
        float2 v11 = *(const float2*)(Arow1 + k0 + 8);
        uint32_t ah0, al0, ah1, al1, ah2, al2, ah3, al3;
        split2(v00.x, v00.y, ah0, al0);
        split2(v10.x, v10.y, ah1, al1);
        split2(v01.x, v01.y, ah2, al2);
        split2(v11.x, v11.y, ah3, al3);

        const uint4* bp = Bp + (size_t)(ntileBase * 16 + S) * 32 + lane;
        #pragma unroll
        for (int t = 0; t < 16; t++) {
            uint4 bb = bp[(size_t)t * 512];   // n-tile stride = 16 S * 32 lanes
            mma16816(acc[t], ah0, ah1, ah2, ah3, bb.x, bb.y);  // Ah * Bh
            mma16816(acc[t], ah0, ah1, ah2, ah3, bb.z, bb.w);  // Ah * Bl
            mma16816(acc[t], al0, al1, al2, al3, bb.x, bb.y);  // Al * Bh
        }
    }

    int row0 = mBase + grp;
    #pragma unroll
    for (int t = 0; t < 16; t++) {
        int n = nh + t * 8 + qp * 2;
        float2 bv = *(const float2*)(bias + n);
        float2 o0 = make_float2(acc[t][0] + bv.x, acc[t][1] + bv.y);
        float2 o1 = make_float2(acc[t][2] + bv.x, acc[t][3] + bv.y);
        *(float2*)&C[(size_t)row0 * 256 + n] = o0;
        *(float2*)&C[(size_t)(row0 + 8) * 256 + n] = o1;
    }
}

// ---------------- sparse masked attention: warp-per-row, online softmax ----------------
// 128 blocks x 512 threads. Block caches kpts_R[b] in SMEM; each warp owns 8 rows.
// Per row: ballot-compact valid keys, then ONE pass over valid keys with
// flash-style rescaling; each gathered nodes_R row is loaded exactly once and
// used for both the logit dot and the weighted accumulation.
__global__ __launch_bounds__(512) void attn_kernel(const float* __restrict__ nodesR,
                                                   const float* __restrict__ kptsL,
                                                   const float* __restrict__ kptsR,
                                                   float* __restrict__ out,
                                                   size_t disp_off, size_t conf_off) {
    __shared__ float s_ku[MM];
    __shared__ float s_kv[MM];
    __shared__ int   s_idx[16][CAPW];

    int tid = threadIdx.x, lane = tid & 31, w = tid >> 5;
    int b = blockIdx.x >> 5;          // 32 blocks per batch
    int tile = blockIdx.x & 31;       // 128 rows per block

    const float* kR = kptsR + (size_t)b * MM * 2;
    for (int m = tid; m < MM; m += 512) {
        float2 p = *(const float2*)(kR + m * 2);
        s_ku[m] = p.x; s_kv[m] = p.y;
    }
    __syncthreads();

    const float* nR = nodesR + (size_t)b * MM * CC;

    #pragma unroll 1
    for (int r = 0; r < 8; r++) {
        int rowg = b * NN + tile * 128 + w * 8 + r;
        float2 kl = *(const float2*)(kptsL + (size_t)rowg * 2);
        float uL = kl.x, vL = kl.y;

        // query row of g_T: 8 floats per lane
        const float* tr = g_T + (size_t)rowg * CC + lane * 8;
        float4 t0 = *(const float4*)tr;
        float4 t1 = *(const float4*)(tr + 4);

        // ---- mask scan + warp compaction (conflict-free LDS) ----
        int nv = 0;
        #pragma unroll 4
        for (int i = 0; i < 128; i++) {
            int m = i * 32 + lane;
            float du = uL - s_ku[m];
            bool val = (fabsf(vL - s_kv[m]) < 3.0f) & (du > 0.0f) & (du < 192.0f);
            unsigned bal = __ballot_sync(0xffffffffu, val);
            if (bal) {
                int p = nv + __popc(bal & ((1u << lane) - 1u));
                if (val && p < CAPW) s_idx[w][p] = m;
                nv += __popc(bal);
            }
        }
        if (nv > CAPW) nv = CAPW;
        __syncwarp();

        float* sOut = g_S + (size_t)rowg * CC + lane * 8;

        if (nv == 0) {
            // all-masked row: softmax over equal logits == uniform 1/M
            const float* mr = g_meanR + b * CC + lane * 8;
            *(float4*)sOut       = *(const float4*)mr;
            *(float4*)(sOut + 4) = *(const float4*)(mr + 4);
            if (lane == 0) {
                out[disp_off + rowg] = uL - g_muR[b];
                out[conf_off + rowg] = 0.0f;
            }
            continue;
        }

        // ---- single pass, online softmax, one-key software prefetch ----
        float mx = -3.0e38f, Z = 0.f, duacc = 0.f;
        float acc[8] = {0.f, 0.f, 0.f, 0.f, 0.f, 0.f, 0.f, 0.f};

        int m0 = s_idx[w][0];
        const float4* pf = (const float4*)(nR + (size_t)m0 * CC) + lane * 2;
        float4 x0 = pf[0], x1 = pf[1];
        float duk = uL - s_ku[m0];

        #pragma unroll 1
        for (int e = 0; e < nv; e++) {
            float4 cx0 = x0, cx1 = x1;
            float cdu = duk;
            if (e + 1 < nv) {
                int m1 = s_idx[w][e + 1];
                const float4* pn = (const float4*)(nR + (size_t)m1 * CC) + lane * 2;
                x0 = pn[0]; x1 = pn[1];
                duk = uL - s_ku[m1];
            }
            float d = cx0.x * t0.x + cx0.y * t0.y + cx0.z * t0.z + cx0.w * t0.w
                    + cx1.x * t1.x + cx1.y * t1.y + cx1.z * t1.z + cx1.w * t1.w;
            #pragma unroll
            for (int off = 16; off; off >>= 1) d += __shfl_xor_sync(0xffffffffu, d, off);

            float nm = fmaxf(mx, d);
            float sc = __expf(mx - nm);   // exp(-inf)=0 on first iter; acc is zero anyway
            float pw = __expf(d - nm);
            Z = Z * sc + pw;
            duacc = duacc * sc + pw * cdu;
            acc[0] = acc[0] * sc + pw * cx0.x;
            acc[1] = acc[1] * sc + pw * cx0.y;
            acc[2] = acc[2] * sc + pw * cx0.z;
            acc[3] = acc[3] * sc + pw * cx0.w;
            acc[4] = acc[4] * sc + pw * cx1.x;
            acc[5] = acc[5] * sc + pw * cx1.y;
            acc[6] = acc[6] * sc + pw * cx1.z;
            acc[7] = acc[7] * sc + pw * cx1.w;
            mx = nm;
        }

        float inv = 1.0f / Z;
        float4 o0 = make_float4(acc[0] * inv, acc[1] * inv, acc[2] * inv, acc[3] * inv);
        float4 o1 = make_float4(acc[4] * inv, acc[5] * inv, acc[6] * inv, acc[7] * inv);
        *(float4*)sOut       = o0;
        *(float4*)(sOut + 4) = o1;
        if (lane == 0) {
            out[disp_off + rowg] = duacc * inv;
            out[conf_off + rowg] = 1.0f;
        }
    }
}

// ---------------- launch ----------------
extern "C" void kernel_launch(void* const* d_in, const int* in_sizes, int n_in,
                              void* d_out, int out_size) {
    (void)in_sizes; (void)n_in;
    const float* nodes_L = (const float*)d_in[0];
    const float* nodes_R = (const float*)d_in[1];
    const float* kpts_L  = (const float*)d_in[2];
    const float* kpts_R  = (const float*)d_in[3];
    const float* Wq = (const float*)d_in[4];
    const float* bq = (const float*)d_in[5];
    const float* Wk = (const float*)d_in[6];
    // bk (d_in[7]) contributes only a per-query-row constant to the logits:
    // softmax-invariant, so it is intentionally unused.
    const float* Wv = (const float*)d_in[8];
    const float* bv = (const float*)d_in[9];
    const float* Wm = (const float*)d_in[10];
    const float* bm = (const float*)d_in[11];
    float* out = (float*)d_out;

    size_t rows = (size_t)BB * NN;
    size_t disp_off = (size_t)out_size - 2 * rows;  // matched [B*N*C] | disp [B*N] | conf [B*N]
    size_t conf_off = disp_off + rows;

    prep_kernel<<<513, 256>>>(Wq, Wk, Wv, Wm, bq, bv, bm);
    pack_kernel<<<64, 512>>>();
    mean_part_kernel<<<dim3(64, BB), 256>>>(nodes_R, kpts_R);
    mean_red_kernel<<<BB, 256>>>();
    tgemm_kernel<false><<<256, 256>>>(nodes_L, nullptr);   // g_T = nodes_L@G + kq
    attn_kernel<<<BB * 32, 512>>>(nodes_R, kpts_L, kpts_R, out, disp_off, conf_off);
    tgemm_kernel<true><<<256, 256>>>(nullptr, out);        // out = g_S@Wvm^T + bout
}

// round 17
// speedup vs baseline: 1.7315x; 1.1904x over previous
#include <cuda_runtime.h>
#include <cstdint>

// Problem constants (fixed shapes)
#define BB 4
#define NN 4096
#define MM 4096
#define CC 256
#define CAPW 128   // max valid keys per row tracked (statistical max ~40)
#define NBUCK 96   // v-buckets of width 4 px (v in [0,384))
#define NCHUNK 16  // warps in bucket_kernel

// ---------------- scratch (static device globals; no allocations) ----------------
// NOTE: referenced ONLY inside device code. Passing a __device__ symbol as a
// kernel argument from host code yields the host shadow address, which GB300's
// ATS silently dereferences to host memory (R8 failure mode).
__device__ float g_Gt[CC * CC];     // Gt[n][k] = G^T, G = (Wq^T Wk)/16
__device__ float g_Wvm[CC * CC];    // Wvm[n][k] = (Wm @ Wv)[n][k]
__device__ float g_kq[CC];          // (Wk^T bq) / 16
__device__ float g_bout[CC];        // Wm @ bv + bm
__device__ uint4 g_GtP[32 * 16 * 32];   // fragment-packed split-bf16 Gt
__device__ uint4 g_WvmP[32 * 16 * 32];  // fragment-packed split-bf16 Wvm
__device__ float g_T[BB * NN * CC]; // nodes_L @ G + kq
__device__ float g_S[BB * NN * CC]; // softmax-weighted sum of nodes_R rows
__device__ float g_meanR[BB * CC];
__device__ float g_muR[BB];
__device__ float g_part[BB * 64 * CC];
__device__ float g_partu[BB * 64];
__device__ int   g_ent[BB][MM];          // key indices grouped by v-bucket
__device__ int   g_bstart[BB][NBUCK + 1];

// ---------------- helpers: fp32 -> (hi, lo) bf16x2 split ----------------
__device__ __forceinline__ void split2(float v0, float v1, uint32_t& h, uint32_t& l) {
    asm("cvt.rn.bf16x2.f32 %0, %1, %2;" : "=r"(h) : "f"(v1), "f"(v0));
    float r0 = v0 - __uint_as_float(h << 16);
    float r1 = v1 - __uint_as_float(h & 0xFFFF0000u);
    asm("cvt.rn.bf16x2.f32 %0, %1, %2;" : "=r"(l) : "f"(r1), "f"(r0));
}

__device__ __forceinline__ void mma16816(float* c, uint32_t a0, uint32_t a1, uint32_t a2,
                                         uint32_t a3, uint32_t b0, uint32_t b1) {
    asm volatile("mma.sync.aligned.m16n8k16.row.col.f32.bf16.bf16.f32 "
                 "{%0,%1,%2,%3}, {%4,%5,%6,%7}, {%8,%9}, {%0,%1,%2,%3};"
                 : "+f"(c[0]), "+f"(c[1]), "+f"(c[2]), "+f"(c[3])
                 : "r"(a0), "r"(a1), "r"(a2), "r"(a3), "r"(b0), "r"(b1));
}

// ---------------- small weight prep: Gt, Wvm, kq, bout ----------------
__global__ void prep_kernel(const float* __restrict__ Wq, const float* __restrict__ Wk,
                            const float* __restrict__ Wv, const float* __restrict__ Wm,
                            const float* __restrict__ bq, const float* __restrict__ bv,
                            const float* __restrict__ bm) {
    int bx = blockIdx.x, j = threadIdx.x;
    if (bx < 256) {
        // Gt[n][k] = (1/16) sum_c Wq[c][k] * Wk[c][n]  (n = bx, k = j)
        float s = 0.f;
        #pragma unroll 8
        for (int c = 0; c < 256; c++) s += Wq[c * 256 + j] * Wk[c * 256 + bx];
        g_Gt[bx * 256 + j] = s * 0.0625f;
    } else if (bx < 512) {
        int i = bx - 256;
        // Wvm[i][j] = sum_k Wm[i][k] * Wv[k][j]
        float s = 0.f;
        #pragma unroll 8
        for (int k = 0; k < 256; k++) s += Wm[i * 256 + k] * Wv[k * 256 + j];
        g_Wvm[i * 256 + j] = s;
    } else {
        float s = 0.f, t = 0.f;
        for (int k = 0; k < 256; k++) {
            s += Wk[k * 256 + j] * bq[k];
            t += Wm[j * 256 + k] * bv[k];
        }
        g_kq[j] = s * 0.0625f;
        g_bout[j] = t + bm[j];
    }
}

// ---------------- pack B matrices into mma fragment layout ----------------
__global__ void pack_kernel() {
    int id = blockIdx.x * 512 + threadIdx.x;   // 64 blocks x 512 = 32768
    int lane = id & 31, S = (id >> 5) & 15, T = (id >> 9) & 31, mat = id >> 14;
    const float* src = mat ? g_Wvm : g_Gt;
    int n = T * 8 + (lane >> 2);
    int kb = S * 16 + (lane & 3) * 2;
    const float* p = src + n * 256 + kb;
    uint32_t h0, l0, h1, l1;
    split2(p[0], p[1], h0, l0);
    split2(p[8], p[9], h1, l1);
    (mat ? g_WvmP : g_GtP)[(T * 16 + S) * 32 + lane] = make_uint4(h0, h1, l0, l1);
}

// ---------------- batch means of nodes_R and u_R (deterministic 2-pass) ----------------
__global__ void mean_part_kernel(const float* __restrict__ nodesR, const float* __restrict__ kptsR) {
    int b = blockIdx.y, p = blockIdx.x, c = threadIdx.x;
    const float* base = nodesR + ((size_t)b * MM + (size_t)p * 64) * CC;
    float s = 0.f;
    #pragma unroll 4
    for (int r = 0; r < 64; r++) s += base[r * CC + c];
    g_part[(b * 64 + p) * CC + c] = s;
    if (c == 0) {
        const float* kb = kptsR + ((size_t)b * MM + (size_t)p * 64) * 2;
        float su = 0.f;
        for (int r = 0; r < 64; r++) su += kb[r * 2];
        g_partu[b * 64 + p] = su;
    }
}

// 32 blocks: (batch, 32-channel chunk). Deterministic fixed-order sums.
__global__ void mean_red_kernel() {
    __shared__ float red[8][32];
    int b = blockIdx.x >> 3, ch = (blockIdx.x & 7) * 32;
    int tid = threadIdx.x;
    int c = ch + (tid & 31), pg = tid >> 5;   // 8 part-groups
    float s = 0.f;
    for (int p = pg; p < 64; p += 8) s += g_part[(b * 64 + p) * CC + c];
    red[pg][tid & 31] = s;
    __syncthreads();
    if (pg == 0) {
        float t = 0.f;
        #pragma unroll
        for (int i = 0; i < 8; i++) t += red[i][tid & 31];
        g_meanR[b * CC + c] = t * (1.0f / MM);
    }
    if ((blockIdx.x & 7) == 0 && tid == 0) {
        float su = 0.f;
        for (int p = 0; p < 64; p++) su += g_partu[b * 64 + p];
        g_muR[b] = su * (1.0f / MM);
    }
}

// ---------------- v-bucket CSR build (one block per batch, deterministic) ----------------
// Entries per bucket end up in ascending key order (chunk-major, in-order fill).
__global__ __launch_bounds__(512) void bucket_kernel(const float* __restrict__ kptsR) {
    __shared__ int s_bk[MM];                  // 16KB bucket id per key
    __shared__ int s_cnt[NBUCK * NCHUNK];     // (bucket, chunk) counts -> offsets
    __shared__ int s_ws[16];
    int b = blockIdx.x;
    int tid = threadIdx.x, lane = tid & 31, w = tid >> 5;
    const float* kR = kptsR + (size_t)b * MM * 2;
    for (int m = tid; m < MM; m += 512) {
        int bk = (int)(kR[m * 2 + 1] * 0.25f);
        s_bk[m] = min(max(bk, 0), NBUCK - 1);
    }
    for (int i = tid; i < NBUCK * NCHUNK; i += 512) s_cnt[i] = 0;
    __syncthreads();
    // count per (bucket, chunk): warp w owns keys [w*256, (w+1)*256)
    #pragma unroll
    for (int i = 0; i < 8; i++)
        atomicAdd(&s_cnt[s_bk[w * 256 + i * 32 + lane] * NCHUNK + w], 1);
    __syncthreads();
    // exclusive scan over 1536 = 512x3 (deterministic)
    int base3 = tid * 3;
    int c0 = s_cnt[base3], c1 = s_cnt[base3 + 1], c2 = s_cnt[base3 + 2];
    int tsum = c0 + c1 + c2, x = tsum;
    #pragma unroll
    for (int off = 1; off < 32; off <<= 1) {
        int y = __shfl_up_sync(0xffffffffu, x, off);
        if (lane >= off) x += y;
    }
    if (lane == 31) s_ws[w] = x;
    __syncthreads();
    if (w == 0 && lane < 16) {
        int v = s_ws[lane], xs = v;
        #pragma unroll
        for (int off = 1; off < 16; off <<= 1) {
            int y = __shfl_up_sync(0xffffu, xs, off);
            if (lane >= off) xs += y;
        }
        s_ws[lane] = xs - v;
    }
    __syncthreads();
    int ex = s_ws[w] + x - tsum;
    s_cnt[base3] = ex;
    s_cnt[base3 + 1] = ex + c0;
    s_cnt[base3 + 2] = ex + c0 + c1;
    __syncthreads();
    for (int bk = tid; bk < NBUCK; bk += 512) g_bstart[b][bk] = s_cnt[bk * NCHUNK];
    if (tid == 0) g_bstart[b][NBUCK] = MM;
    __syncthreads();
    // in-order fill: only warp w touches chunk w -> sequential, deterministic
    #pragma unroll
    for (int i = 0; i < 8; i++) {
        int m = w * 256 + i * 32 + lane;
        int bk = s_bk[m];
        unsigned mask = __match_any_sync(0xffffffffu, bk);
        int leader = __ffs(mask) - 1;
        int rank = __popc(mask & ((1u << lane) - 1));
        int base;
        if (lane == leader) base = atomicAdd(&s_cnt[bk * NCHUNK + w], __popc(mask));
        base = __shfl_sync(0xffffffffu, base, leader);
        g_ent[b][base + rank] = m;
    }
}

// ---------------- split-bf16 tensor-core GEMM ----------------
// SECOND=false: g_T = Aparam @ Gt^T + kq      (Aparam = nodes_L)
// SECOND=true : Cparam = g_S @ Wvm^T + bout   (Cparam = d_out)
template <bool SECOND>
__global__ __launch_bounds__(256) void tgemm_kernel(const float* __restrict__ Aparam,
                                                    float* __restrict__ Cparam) {
    const float* A    = SECOND ? g_S : Aparam;
    const uint4* Bp   = SECOND ? g_WvmP : g_GtP;
    const float* bias = SECOND ? g_bout : g_kq;
    float*       C    = SECOND ? Cparam : g_T;

    int tid = threadIdx.x, lane = tid & 31, wid = tid >> 5;
    int grp = lane >> 2, qp = lane & 3;
    int mBase = blockIdx.x * 64 + (wid & 3) * 16;
    int ntileBase = (wid >> 2) * 16;
    int nh = (wid >> 2) * 128;

    const float* Arow0 = A + (size_t)(mBase + grp) * 256 + qp * 2;
    const float* Arow1 = Arow0 + 8 * 256;

    float acc[16][4];
    #pragma unroll
    for (int t = 0; t < 16; t++)
        #pragma unroll
        for (int i = 0; i < 4; i++) acc[t][i] = 0.f;

    #pragma unroll 1
    for (int S = 0; S < 16; S++) {
        int k0 = S * 16;
        float2 v00 = *(const float2*)(Arow0 + k0);
        float2 v10 = *(const float2*)(Arow1 + k0);
        float2 v01 = *(const float2*)(Arow0 + k0 + 8);
        float2 v11 = *(const float2*)(Arow1 + k0 + 8);
        uint32_t ah0, al0, ah1, al1, ah2, al2, ah3, al3;
        split2(v00.x, v00.y, ah0, al0);
        split2(v10.x, v10.y, ah1, al1);
        split2(v01.x, v01.y, ah2, al2);
        split2(v11.x, v11.y, ah3, al3);

        const uint4* bp = Bp + (size_t)(ntileBase * 16 + S) * 32 + lane;
        #pragma unroll
        for (int t = 0; t < 16; t++) {
            uint4 bb = bp[(size_t)t * 512];
            mma16816(acc[t], ah0, ah1, ah2, ah3, bb.x, bb.y);  // Ah * Bh
            mma16816(acc[t], ah0, ah1, ah2, ah3, bb.z, bb.w);  // Ah * Bl
            mma16816(acc[t], al0, al1, al2, al3, bb.x, bb.y);  // Al * Bh
        }
    }

    int row0 = mBase + grp;
    #pragma unroll
    for (int t = 0; t < 16; t++) {
        int n = nh + t * 8 + qp * 2;
        float2 bv = *(const float2*)(bias + n);
        float2 o0 = make_float2(acc[t][0] + bv.x, acc[t][1] + bv.y);
        float2 o1 = make_float2(acc[t][2] + bv.x, acc[t][3] + bv.y);
        *(float2*)&C[(size_t)row0 * 256 + n] = o0;
        *(float2*)&C[(size_t)(row0 + 8) * 256 + n] = o1;
    }
}

// ---------------- sparse masked attention: warp-per-row over v-bucket candidates ----------------
// 256 blocks x 256 threads; block = 64 rows of one batch; warp owns 8 rows.
// Candidates come from <=3 v-buckets (~128 keys) instead of all 4096.
__global__ __launch_bounds__(256) void attn_kernel(const float* __restrict__ nodesR,
                                                   const float* __restrict__ kptsL,
                                                   const float* __restrict__ kptsR,
                                                   float* __restrict__ out,
                                                   size_t disp_off, size_t conf_off) {
    __shared__ float s_ku[MM];
    __shared__ float s_kv[MM];
    __shared__ int   s_idx[8][CAPW];
    __shared__ int   s_bs[NBUCK + 1];

    int tid = threadIdx.x, lane = tid & 31, w = tid >> 5;
    int b = blockIdx.x >> 6;          // 64 blocks per batch
    int tile = blockIdx.x & 63;       // 64 rows per block

    const float* kR = kptsR + (size_t)b * MM * 2;
    for (int m = tid; m < MM; m += 256) {
        float2 p = *(const float2*)(kR + m * 2);
        s_ku[m] = p.x; s_kv[m] = p.y;
    }
    for (int i = tid; i <= NBUCK; i += 256) s_bs[i] = g_bstart[b][i];
    __syncthreads();

    const float* nR = nodesR + (size_t)b * MM * CC;
    const int* ents = g_ent[b];

    #pragma unroll 1
    for (int r = 0; r < 8; r++) {
        int rowg = b * NN + tile * 64 + w * 8 + r;
        float2 kl = *(const float2*)(kptsL + (size_t)rowg * 2);
        float uL = kl.x, vL = kl.y;

        const float* tr = g_T + (size_t)rowg * CC + lane * 8;
        float4 t0 = *(const float4*)tr;
        float4 t1 = *(const float4*)(tr + 4);

        // ---- candidate scan over v-buckets + warp compaction ----
        int bLo = max(0, (int)floorf((vL - 3.0f) * 0.25f));
        int bHi = min(NBUCK - 1, (int)floorf((vL + 3.0f) * 0.25f));
        int e0 = s_bs[bLo], e1 = s_bs[bHi + 1];
        int nv = 0;
        for (int off = e0; off < e1; off += 32) {
            int idx = off + lane;
            bool val = false;
            int m = 0;
            if (idx < e1) {
                m = ents[idx];
                float du = uL - s_ku[m];
                val = (fabsf(vL - s_kv[m]) < 3.0f) & (du > 0.0f) & (du < 192.0f);
            }
            unsigned bal = __ballot_sync(0xffffffffu, val);
            int p = nv + __popc(bal & ((1u << lane) - 1u));
            if (val && p < CAPW) s_idx[w][p] = m;
            nv += __popc(bal);
        }
        if (nv > CAPW) nv = CAPW;
        __syncwarp();

        float* sOut = g_S + (size_t)rowg * CC + lane * 8;

        if (nv == 0) {
            const float* mr = g_meanR + b * CC + lane * 8;
            *(float4*)sOut       = *(const float4*)mr;
            *(float4*)(sOut + 4) = *(const float4*)(mr + 4);
            if (lane == 0) {
                out[disp_off + rowg] = uL - g_muR[b];
                out[conf_off + rowg] = 0.0f;
            }
            continue;
        }

        // ---- single pass, online softmax, one-key software prefetch ----
        float mx = -3.0e38f, Z = 0.f, duacc = 0.f;
        float acc[8] = {0.f, 0.f, 0.f, 0.f, 0.f, 0.f, 0.f, 0.f};

        int m0 = s_idx[w][0];
        const float4* pf = (const float4*)(nR + (size_t)m0 * CC) + lane * 2;
        float4 x0 = pf[0], x1 = pf[1];
        float duk = uL - s_ku[m0];

        #pragma unroll 1
        for (int e = 0; e < nv; e++) {
            float4 cx0 = x0, cx1 = x1;
            float cdu = duk;
            if (e + 1 < nv) {
                int m1 = s_idx[w][e + 1];
                const float4* pn = (const float4*)(nR + (size_t)m1 * CC) + lane * 2;
                x0 = pn[0]; x1 = pn[1];
                duk = uL - s_ku[m1];
            }
            float d = cx0.x * t0.x + cx0.y * t0.y + cx0.z * t0.z + cx0.w * t0.w
                    + cx1.x * t1.x + cx1.y * t1.y + cx1.z * t1.z + cx1.w * t1.w;
            #pragma unroll
            for (int off = 16; off; off >>= 1) d += __shfl_xor_sync(0xffffffffu, d, off);

            float nm = fmaxf(mx, d);
            float sc = __expf(mx - nm);
            float pw = __expf(d - nm);
            Z = Z * sc + pw;
            duacc = duacc * sc + pw * cdu;
            acc[0] = acc[0] * sc + pw * cx0.x;
            acc[1] = acc[1] * sc + pw * cx0.y;
            acc[2] = acc[2] * sc + pw * cx0.z;
            acc[3] = acc[3] * sc + pw * cx0.w;
            acc[4] = acc[4] * sc + pw * cx1.x;
            acc[5] = acc[5] * sc + pw * cx1.y;
            acc[6] = acc[6] * sc + pw * cx1.z;
            acc[7] = acc[7] * sc + pw * cx1.w;
            mx = nm;
        }

        float inv = 1.0f / Z;
        float4 o0 = make_float4(acc[0] * inv, acc[1] * inv, acc[2] * inv, acc[3] * inv);
        float4 o1 = make_float4(acc[4] * inv, acc[5] * inv, acc[6] * inv, acc[7] * inv);
        *(float4*)sOut       = o0;
        *(float4*)(sOut + 4) = o1;
        if (lane == 0) {
            out[disp_off + rowg] = duacc * inv;
            out[conf_off + rowg] = 1.0f;
        }
    }
}

// ---------------- launch ----------------
extern "C" void kernel_launch(void* const* d_in, const int* in_sizes, int n_in,
                              void* d_out, int out_size) {
    (void)in_sizes; (void)n_in;
    const float* nodes_L = (const float*)d_in[0];
    const float* nodes_R = (const float*)d_in[1];
    const float* kpts_L  = (const float*)d_in[2];
    const float* kpts_R  = (const float*)d_in[3];
    const float* Wq = (const float*)d_in[4];
    const float* bq = (const float*)d_in[5];
    const float* Wk = (const float*)d_in[6];
    // bk (d_in[7]) is softmax-invariant (per-query-row constant); unused.
    const float* Wv = (const float*)d_in[8];
    const float* bv = (const float*)d_in[9];
    const float* Wm = (const float*)d_in[10];
    const float* bm = (const float*)d_in[11];
    float* out = (float*)d_out;

    size_t rows = (size_t)BB * NN;
    size_t disp_off = (size_t)out_size - 2 * rows;  // matched [B*N*C] | disp [B*N] | conf [B*N]
    size_t conf_off = disp_off + rows;

    prep_kernel<<<513, 256>>>(Wq, Wk, Wv, Wm, bq, bv, bm);
    pack_kernel<<<64, 512>>>();
    mean_part_kernel<<<dim3(64, BB), 256>>>(nodes_R, kpts_R);
    mean_red_kernel<<<BB * 8, 256>>>();
    bucket_kernel<<<BB, 512>>>(kpts_R);
    tgemm_kernel<false><<<256, 256>>>(nodes_L, nullptr);   // g_T = nodes_L@G + kq
    attn_kernel<<<BB * 64, 256>>>(nodes_R, kpts_L, kpts_R, out, disp_off, conf_off);
    tgemm_kernel<true><<<256, 256>>>(nullptr, out);        // out = g_S@Wvm^T + bout
}